// round 13
// baseline (speedup 1.0000x reference)
#include <cuda_runtime.h>
#include <cuda_bf16.h>
#include <cstdint>

#define BB   4
#define NQ   16384
#define MM   4096
#define CC   256
#define BN   (BB*NQ)

// ---------------- scratch (static device memory; no allocations) ----------------
__device__ float4 g_w[BN];          // per-query 3 weights
__device__ int4   g_i[BN];          // per-query 3 neighbor indices
__device__ float  g_ft[BB*MM*CC];   // transposed features (B, M, C), 16.8 MB

static __device__ __forceinline__ float f_inf() { return __int_as_float(0x7f800000); }

// Squared norm with LLVM DAGCombiner contraction order:
//   t = fma(x,x, round(y*y));  su = fma(z,z, t)
static __device__ __forceinline__ float norm2_llvm(float x, float y, float z) {
    return fmaf(z, z, fmaf(x, x, __fmul_rn(y, y)));
}

// ---------------- kernel 1: transpose feats (B,C,M) -> (B,M,C) ----------------
__global__ void __launch_bounds__(256) tr_kernel(const float* __restrict__ f) {
    __shared__ float t[32][33];
    int b  = blockIdx.z;
    int m0 = blockIdx.x * 32;
    int c0 = blockIdx.y * 32;
    const float* fb = f + (size_t)b * CC * MM;
#pragma unroll
    for (int i = threadIdx.y; i < 32; i += 8)
        t[i][threadIdx.x] = fb[(size_t)(c0 + i) * MM + m0 + threadIdx.x];
    __syncthreads();
    float* fo = g_ft + (size_t)b * MM * CC;
#pragma unroll
    for (int i = threadIdx.y; i < 32; i += 8)
        fo[(size_t)(m0 + i) * CC + c0 + threadIdx.x] = t[threadIdx.x][i];
}

// ---------------- kernel 2: 3-NN + inverse-distance weights ----------------
// Fast screen: v = kk - 2*u.k via 3 FMAs (pre-negated -2u). Exact (rare) path
// reproduces the inferred reference rounding:
//   su,kk = fma(z,z, fma(x,x, y*y))                (LLVM contraction order)
//   dot   = fma(a2,b2, fma(a1,b1, a0*b0))          (ascending FMA chain, acc=0)
//   d2    = (su + kk) - 2*dot                      (2*dot exact; one subtract round)
__device__ __forceinline__ void knn_upd(float d2, int gj,
                                        float& b0, float& b1, float& b2,
                                        int& i0, int& i1, int& i2) {
    if (d2 < b2) {
        if (d2 < b1) {
            b2 = b1; i2 = i1;
            if (d2 < b0) { b1 = b0; i1 = i0; b0 = d2; i0 = gj; }
            else         { b1 = d2; i1 = gj; }
        } else { b2 = d2; i2 = gj; }
    }
}

#define KNN_PROC(kp, gj) do {                                                  \
    float _dt = fmaf((kp).z, uz, fmaf((kp).y, uy, __fmul_rn((kp).x, ux)));     \
    float _d2 = __fadd_rn(__fadd_rn(su, (kp).w), -__fmul_rn(2.0f, _dt));       \
    knn_upd(_d2, (gj), b0, b1, b2, i0, i1, i2);                                \
} while (0)

__global__ void __launch_bounds__(256) knn_kernel(const float* __restrict__ unknown,
                                                  const float* __restrict__ known) {
    __shared__ float4 sk[2048];   // 32 KB chunk of known points (x,y,z,|k|^2)

    int qid = blockIdx.x * 256 + threadIdx.x;   // all threads of a block share batch b
    int b   = qid >> 14;                        // / NQ
    const float* kb = known + (size_t)b * MM * 3;

    float ux = unknown[(size_t)qid * 3 + 0];
    float uy = unknown[(size_t)qid * 3 + 1];
    float uz = unknown[(size_t)qid * 3 + 2];
    float su = norm2_llvm(ux, uy, uz);
    float nux = __fmul_rn(-2.0f, ux);
    float nuy = __fmul_rn(-2.0f, uy);
    float nuz = __fmul_rn(-2.0f, uz);

    float b0 = f_inf(), b1 = f_inf(), b2 = f_inf();
    int   i0 = 0, i1 = 0, i2 = 0;
    float thr = f_inf();   // screen threshold in v-space: (b2 - su) + margin

    for (int ch = 0; ch < 2; ch++) {
        int base = ch * 2048;
        __syncthreads();
        // cooperative load of this chunk of known points
        for (int p = threadIdx.x; p < 2048; p += 256) {
            float kx = kb[(size_t)(base + p) * 3 + 0];
            float ky = kb[(size_t)(base + p) * 3 + 1];
            float kz = kb[(size_t)(base + p) * 3 + 2];
            sk[p] = make_float4(kx, ky, kz, norm2_llvm(kx, ky, kz));
        }
        __syncthreads();

        for (int j = 0; j < 2048; j += 4) {
            float4 k0 = sk[j + 0];
            float4 k1 = sk[j + 1];
            float4 k2 = sk[j + 2];
            float4 k3 = sk[j + 3];
            float v0 = fmaf(k0.x, nux, fmaf(k0.y, nuy, fmaf(k0.z, nuz, k0.w)));
            float v1 = fmaf(k1.x, nux, fmaf(k1.y, nuy, fmaf(k1.z, nuz, k1.w)));
            float v2 = fmaf(k2.x, nux, fmaf(k2.y, nuy, fmaf(k2.z, nuz, k2.w)));
            float v3 = fmaf(k3.x, nux, fmaf(k3.y, nuy, fmaf(k3.z, nuz, k3.w)));
            float vm = fminf(fminf(v0, v1), fminf(v2, v3));
            if (vm < thr) {   // rare slow path: exact reference-rounded d2 + insert
                KNN_PROC(k0, base + j + 0);
                KNN_PROC(k1, base + j + 1);
                KNN_PROC(k2, base + j + 2);
                KNN_PROC(k3, base + j + 3);
                thr = __fadd_rn(__fadd_rn(b2, -su), 6e-6f);
            }
        }
    }

    // weights: dist = sqrt(max(d2,0)); r = 1/(dist+eps); w = r / sum(r)
    float dd0 = sqrtf(fmaxf(b0, 0.0f));
    float dd1 = sqrtf(fmaxf(b1, 0.0f));
    float dd2 = sqrtf(fmaxf(b2, 0.0f));
    float r0 = __fdiv_rn(1.0f, __fadd_rn(dd0, 1e-8f));
    float r1 = __fdiv_rn(1.0f, __fadd_rn(dd1, 1e-8f));
    float r2 = __fdiv_rn(1.0f, __fadd_rn(dd2, 1e-8f));
    float ws = __fadd_rn(__fadd_rn(r0, r1), r2);
    g_w[qid] = make_float4(__fdiv_rn(r0, ws), __fdiv_rn(r1, ws),
                           __fdiv_rn(r2, ws), 0.0f);
    g_i[qid] = make_int4(i0, i1, i2, 0);
}

// ---------------- kernel 3: coalesced gather + blend, transposed write ----------------
// Block = 256 threads (one per channel) handling a tile of 32 queries.
// Reads from g_ft are fully coalesced 128B rows; writes go via smem so lanes
// map to contiguous n in the (B,C,n) output.
__global__ void __launch_bounds__(256) gather_kernel(float* __restrict__ out) {
    __shared__ float  tile[CC][33];   // [c][q], pad to kill bank conflicts
    __shared__ float4 sw[32];
    __shared__ int4   si[32];

    int blk = blockIdx.x;
    int b   = blk >> 9;          // NQ/32 = 512 blocks per batch
    int n0  = (blk & 511) << 5;
    int tid = threadIdx.x;

    if (tid < 32) {
        sw[tid] = g_w[b * NQ + n0 + tid];
        si[tid] = g_i[b * NQ + n0 + tid];
    }
    __syncthreads();

    const float* ftb = g_ft + (size_t)b * MM * CC;
    int c = tid;
#pragma unroll 4
    for (int q = 0; q < 32; q++) {
        int4   jj = si[q];
        float4 ww = sw[q];
        float f0 = __ldg(&ftb[(size_t)jj.x * CC + c]);
        float f1 = __ldg(&ftb[(size_t)jj.y * CC + c]);
        float f2 = __ldg(&ftb[(size_t)jj.z * CC + c]);
        // reduce-style contracted blend: fma(f2,w2, fma(f1,w1, f0*w0)) ascending
        tile[c][q] = fmaf(f2, ww.z, fmaf(f1, ww.y, __fmul_rn(f0, ww.x)));
    }
    __syncthreads();

    float* ob = out + (size_t)b * CC * NQ;
    int wrp = tid >> 5, lane = tid & 31;
#pragma unroll
    for (int r = wrp; r < CC; r += 8)
        ob[(size_t)r * NQ + n0 + lane] = tile[r][lane];
}

// ---------------- launch ----------------
extern "C" void kernel_launch(void* const* d_in, const int* in_sizes, int n_in,
                              void* d_out, int out_size) {
    const float* unknown = (const float*)d_in[0];   // (B, n, 3)
    const float* known   = (const float*)d_in[1];   // (B, m, 3)
    const float* feats   = (const float*)d_in[2];   // (B, C, m)
    float* out = (float*)d_out;                     // (B, C, n)

    dim3 tb(32, 8);
    dim3 tg(MM / 32, CC / 32, BB);
    tr_kernel<<<tg, tb>>>(feats);

    knn_kernel<<<BN / 256, 256>>>(unknown, known);

    gather_kernel<<<BN / 32, 256>>>(out);
}